// round 4
// baseline (speedup 1.0000x reference)
#include <cuda_runtime.h>
#include <cstdint>

// ---------------------------------------------------------------------------
// RowLSTM: i_s precompute (7x7 convs) -> sequential row scan (LSTM) -> 1x1 out
//
//   kA: i_s [B][H][160][W], 4-oc ILP blocking
//   kB: scan. 16 clusters x 8 CTAs; 640 threads = (40 hc) x (8 w) x (2 side).
//       side pairs live in adjacent lanes -> gate exchange by shfl.xor(1).
//       One __syncthreads per layer. Weights resident in SMEM. Halo (h,c)
//       exchange via DSMEM push (st.shared::cluster) into parity buffers.
//       Pushes stop at t==HH-2 (row-63 halos unread; avoids writes into
//       exited CTAs -- the R3 crash).
//   kC: out = relu(W_out @ hidden + b)
//   kD: no-op (profiler window alignment)
// ---------------------------------------------------------------------------

#define HIDDEN   40
#define NLAYERS  7
#define BATCH    16
#define HH       64
#define WW       64
#define CPB      8
#define WPC      8
#define TPB_B    640

__device__ float g_is[(size_t)BATCH * HH * 160 * WW];
__device__ float g_hidden[(size_t)BATCH * HH * HIDDEN * WW];

__device__ __forceinline__ float tanh_(float x) {
    float ax = fabsf(x);
    float e = __expf(2.0f * ax);
    float t = 1.0f - __fdividef(2.0f, e + 1.0f);
    return copysignf(t, x);
}
__device__ __forceinline__ float dot4(float4 a, float4 b) {
    return a.x * b.x + a.y * b.y + a.z * b.z + a.w * b.w;
}
__device__ __forceinline__ void cluster_sync_() {
    asm volatile("barrier.cluster.arrive.aligned;" ::: "memory");
    asm volatile("barrier.cluster.wait.aligned;" ::: "memory");
}
__device__ __forceinline__ void push_remote(float* p, uint32_t rank, float v) {
    uint32_t l = (uint32_t)__cvta_generic_to_shared(p);
    uint32_t r;
    asm volatile("mapa.shared::cluster.u32 %0, %1, %2;" : "=r"(r) : "r"(l), "r"(rank));
    asm volatile("st.shared::cluster.f32 [%0], %1;" :: "r"(r), "f"(v) : "memory");
}

// ===========================================================================
// Kernel A
// ===========================================================================
__global__ void __launch_bounds__(256) kA(
    const float* __restrict__ inp, const float* __restrict__ tgt,
    const float* __restrict__ w_is, const float* __restrict__ b_is,
    const float* __restrict__ w_cis, const float* __restrict__ b_cis)
{
    __shared__ float sW[160 * 52];
    __shared__ float sB[160];
    __shared__ float sT[22][22];

    const int b   = blockIdx.z;
    const int ty0 = blockIdx.y * 16;
    const int tx0 = blockIdx.x * 16;
    const int tid = threadIdx.x;
    const int ty  = tid / 16;
    const int tx  = tid % 16;

    for (int i = tid; i < 160 * 52; i += 256) {
        int oc = i / 52, j = i % 52;
        float v = 0.0f;
        if (j < 49) {
            int r = j / 7, s = j % 7;
            if (oc < 80) v = w_cis[oc * 49 + j];
            else {
                bool keep = (r < 3) || (r == 3 && s < 3);
                v = keep ? w_is[(oc - 80) * 49 + j] : 0.0f;
            }
        }
        sW[i] = v;
    }
    for (int i = tid; i < 160; i += 256)
        sB[i] = (i < 80) ? b_cis[i] : b_is[i - 80];

    for (int pass = 0; pass < 2; ++pass) {
        __syncthreads();
        const float* src = pass ? tgt : inp;
        for (int i = tid; i < 22 * 22; i += 256) {
            int r = i / 22, cc = i % 22;
            int y = ty0 - 3 + r, x = tx0 - 3 + cc;
            sT[r][cc] = (y >= 0 && y < HH && x >= 0 && x < WW)
                            ? src[((size_t)b * HH + y) * WW + x] : 0.0f;
        }
        __syncthreads();

        float v[52];
#pragma unroll
        for (int r = 0; r < 7; ++r)
#pragma unroll
            for (int s = 0; s < 7; ++s)
                v[r * 7 + s] = sT[ty + r][tx + s];
        v[49] = 0.0f; v[50] = 0.0f; v[51] = 0.0f;

        const int ocbase = pass * 80;
        float* dst = &g_is[(((size_t)b * HH + (ty0 + ty)) * 160) * WW + (tx0 + tx)];
        for (int oc = ocbase; oc < ocbase + 80; oc += 4) {
            float a0 = sB[oc], a1 = sB[oc + 1], a2 = sB[oc + 2], a3 = sB[oc + 3];
            const float4* w0 = (const float4*)&sW[(oc + 0) * 52];
            const float4* w1 = (const float4*)&sW[(oc + 1) * 52];
            const float4* w2 = (const float4*)&sW[(oc + 2) * 52];
            const float4* w3 = (const float4*)&sW[(oc + 3) * 52];
#pragma unroll 4
            for (int jj = 0; jj < 13; ++jj) {
                float4 W0 = w0[jj], W1 = w1[jj], W2 = w2[jj], W3 = w3[jj];
                float v0 = v[4 * jj], v1 = v[4 * jj + 1], v2 = v[4 * jj + 2], v3 = v[4 * jj + 3];
                a0 += W0.x * v0 + W0.y * v1 + W0.z * v2 + W0.w * v3;
                a1 += W1.x * v0 + W1.y * v1 + W1.z * v2 + W1.w * v3;
                a2 += W2.x * v0 + W2.y * v1 + W2.z * v2 + W2.w * v3;
                a3 += W3.x * v0 + W3.y * v1 + W3.z * v2 + W3.w * v3;
            }
            dst[(size_t)(oc + 0) * WW] = a0;
            dst[(size_t)(oc + 1) * WW] = a1;
            dst[(size_t)(oc + 2) * WW] = a2;
            dst[(size_t)(oc + 3) * WW] = a3;
        }
    }
}

// ===========================================================================
// Kernel B: 128 CTAs (16 clusters of 8), 640 threads.
// tid = hc*16 + w*2 + side.  side0 -> gates i,f + owns c,h.  side1 -> o,g.
// ===========================================================================
#define SMEMB_FLOATS (44800 + 9600 + 1120 + 80 + 400 + 400 + 400 + 320 + 160 + 160)
#define SMEMB_BYTES  (SMEMB_FLOATS * 4)

__global__ void __cluster_dims__(CPB, 1, 1) __launch_bounds__(TPB_B, 1) kB(
    const float* __restrict__ w_cell, const float* __restrict__ b_cell,
    const float* __restrict__ w_rh, const float* __restrict__ b_rh,
    const float* __restrict__ w_rc, const float* __restrict__ b_rc)
{
    extern __shared__ float sm[];
    float* sWc   = sm;                 // [7][160][40]
    float* sWr   = sWc + 44800;        // [2][40 oc][3 tap][40 ic]
    float* sBc   = sWr + 9600;         // [7][160]
    float* sBr   = sBc + 1120;         // [2][40]
    float* sHa   = sBr + 80;           // [10][40]  rows 0/9 = halo
    float* sHb   = sHa + 400;          // [10][40]
    float* sC    = sHb + 400;          // [10][40]
    float* sCn   = sC + 400;           // [8][40]
    float* hHalo = sCn + 320;          // [2 parity][2 side(0=my-left,1=my-right)][40]
    float* cHalo = hHalo + 160;        // [2][2][40]

    const int tid   = threadIdx.x;
    const int side  = tid & 1;
    const int w     = (tid >> 1) & 7;
    const int hc    = tid >> 4;
    const int b     = blockIdx.x >> 3;
    const int crank = blockIdx.x & 7;
    const int wg    = crank * WPC + w;

    // ---- stage weights -----------------------------------------------------
    for (int i = tid; i < 44800; i += TPB_B) sWc[i] = w_cell[i];
    for (int i = tid; i < 9600; i += TPB_B) {
        int cv = i / 4800, j = i % 4800;
        int oc = j / 120, j2 = j % 120, tap = j2 / 40, ic = j2 % 40;
        const float* src = cv ? w_rc : w_rh;
        sWr[i] = src[oc * 120 + ic * 3 + tap];
    }
    for (int i = tid; i < 1120; i += TPB_B) sBc[i] = b_cell[i];
    for (int i = tid; i < 80; i += TPB_B) sBr[i] = (i < 40) ? b_rh[i] : b_rc[i - 40];
    for (int i = tid; i < 1200; i += TPB_B) sHa[i] = 0.0f;   // sHa,sHb,sC
    __syncthreads();

    const int rowA = side * 80 + hc;   // i (side0) / o (side1)
    const int rowB = rowA + 40;        // f (side0) / g (side1)
    const float* xbase = g_is + ((size_t)b * HH) * 160 * WW + (size_t)rowA * WW + wg;

    float xA = xbase[0];
    float xB = xbase[40 * WW];

    float c = 0.0f, hval = 0.0f;

    for (int t = 0; t < HH; ++t) {
        // prefetch next row's x
        float nxA = 0.0f, nxB = 0.0f;
        if (t + 1 < HH) {
            const float* xp = xbase + (size_t)(t + 1) * 160 * WW;
            nxA = xp[0];
            nxB = xp[40 * WW];
        }

        if (t > 0) {
            cluster_sync_();           // remote halo pushes + local smem visible
            int p = (t - 1) & 1;
            if (side == 0) {           // copy halo buffers into conv windows
                if (w == 0)      sHa[0 * 40 + hc] = (crank > 0) ? hHalo[(p * 2 + 0) * 40 + hc] : 0.0f;
                else if (w == 1) sC [0 * 40 + hc] = (crank > 0) ? cHalo[(p * 2 + 0) * 40 + hc] : 0.0f;
                else if (w == 2) sHa[9 * 40 + hc] = (crank < 7) ? hHalo[(p * 2 + 1) * 40 + hc] : 0.0f;
                else if (w == 3) sC [9 * 40 + hc] = (crank < 7) ? cHalo[(p * 2 + 1) * 40 + hc] : 0.0f;
            }
        }
        __syncthreads();   // [1] halos in place

        // ---- row conv: side0 h-conv, side1 c-conv --------------------------
        {
            const float4* V4 = (const float4*)(side ? sC : sHa);
            const float4* Wb = (const float4*)(sWr + side * 4800 + hc * 120);
            float acc = sBr[side * 40 + hc];
#pragma unroll 2
            for (int icc = 0; icc < 10; ++icc) {
                acc += dot4(Wb[icc],      V4[w * 10 + icc])
                     + dot4(Wb[10 + icc], V4[(w + 1) * 10 + icc])
                     + dot4(Wb[20 + icc], V4[(w + 2) * 10 + icc]);
            }
            if (side == 0) sHb[(1 + w) * 40 + hc] = acc;
            else           sCn[w * 40 + hc] = acc;
        }
        __syncthreads();   // [2] sHb + sCn ready

        if (side == 0) c = sCn[w * 40 + hc];

        // ---- 7 LSTM layers, one barrier each --------------------------------
#pragma unroll 1
        for (int l = 0; l < NLAYERS; ++l) {
            float* rbuf = (l & 1) ? sHa : sHb;
            float* wbuf = (l & 1) ? sHb : sHa;

            float aA = sBc[l * 160 + rowA] + xA;
            float aB = sBc[l * 160 + rowB] + xB;

            const float4* WA = (const float4*)(sWc + (l * 160 + rowA) * 40);
            const float4* WB = (const float4*)(sWc + (l * 160 + rowB) * 40);
            const float4* hv = (const float4*)(rbuf + (1 + w) * 40);
#pragma unroll 5
            for (int kk = 0; kk < 10; ++kk) {
                float4 h4 = hv[kk];
                aA += dot4(WA[kk], h4);
                aB += dot4(WB[kk], h4);
            }
            // side0: gA=sig(aA)=i, gB=sig(aB)=f ; side1: gA=sig(aA)=o, gB=tanh(aB)=g
            float tA = tanh_(0.5f * aA);
            float gA = 0.5f + 0.5f * tA;
            float xBs = side ? aB : 0.5f * aB;
            float tB = tanh_(xBs);
            float gB = side ? tB : 0.5f + 0.5f * tB;

            float o_ = __shfl_xor_sync(0xffffffffu, gA, 1);
            float g_ = __shfl_xor_sync(0xffffffffu, gB, 1);

            if (side == 0) {
                c = gB * c + gA * g_;
                hval = o_ * tanh_(c);
                wbuf[(1 + w) * 40 + hc] = hval;
            }
            __syncthreads();
        }
        // final h in sHa (layer 6 wrote sHa) -> next row h-conv reads sHa ✓

        if (side == 0) {
            sC[(1 + w) * 40 + hc] = c;
            g_hidden[(((size_t)b * HH + t) * HIDDEN + hc) * WW + wg] = hval;

            // DSMEM pushes only while every neighbor is guaranteed alive:
            // row-(HH-1) halos are never read, and a reader's cluster barrier
            // at row t+1 keeps all CTAs resident until consumption.
            if (t < HH - 1) {
                int p2 = t & 1;
                if (w == 7 && crank < 7) {     // fill right neighbor's LEFT halo
                    push_remote(&hHalo[(p2 * 2 + 0) * 40 + hc], (uint32_t)(crank + 1), hval);
                    push_remote(&cHalo[(p2 * 2 + 0) * 40 + hc], (uint32_t)(crank + 1), c);
                }
                if (w == 0 && crank > 0) {     // fill left neighbor's RIGHT halo
                    push_remote(&hHalo[(p2 * 2 + 1) * 40 + hc], (uint32_t)(crank - 1), hval);
                    push_remote(&cHalo[(p2 * 2 + 1) * 40 + hc], (uint32_t)(crank - 1), c);
                }
            }
        }

        xA = nxA; xB = nxB;
    }
}

// ===========================================================================
// Kernel C
// ===========================================================================
__global__ void __launch_bounds__(256) kC(
    const float* __restrict__ w_out, const float* __restrict__ b_out,
    float* __restrict__ out)
{
    __shared__ float sWo[256 * 40];
    __shared__ float sBo[256];

    const int y = blockIdx.x;
    const int b = blockIdx.y;
    const int tid = threadIdx.x;

    for (int i = tid; i < 256 * 40; i += 256) sWo[i] = w_out[i];
    if (tid < 256) sBo[tid] = b_out[tid];
    __syncthreads();

    const int x   = tid & 63;
    const int ocg = tid >> 6;

    float hr[40];
    const float* hid = g_hidden + (((size_t)b * HH + y) * HIDDEN) * WW + x;
#pragma unroll
    for (int k = 0; k < 40; ++k) hr[k] = hid[k * WW];

    const int oc0 = ocg * 64;
#pragma unroll 2
    for (int oc = oc0; oc < oc0 + 64; ++oc) {
        float a = sBo[oc];
        const float4* w4 = (const float4*)&sWo[oc * 40];
#pragma unroll
        for (int kk = 0; kk < 10; ++kk) {
            float4 W = w4[kk];
            a += W.x * hr[4 * kk + 0] + W.y * hr[4 * kk + 1]
               + W.z * hr[4 * kk + 2] + W.w * hr[4 * kk + 3];
        }
        out[(((size_t)b * 256 + oc) * HH + y) * WW + x] = fmaxf(a, 0.0f);
    }
}

__global__ void kD() {}

// ===========================================================================
// launcher
// ===========================================================================
extern "C" void kernel_launch(void* const* d_in, const int* in_sizes, int n_in,
                              void* d_out, int out_size)
{
    const float* inp    = (const float*)d_in[0];
    const float* tgt    = (const float*)d_in[1];
    const float* w_is   = (const float*)d_in[2];
    const float* b_is   = (const float*)d_in[3];
    const float* w_cis  = (const float*)d_in[4];
    const float* b_cis  = (const float*)d_in[5];
    const float* w_rh   = (const float*)d_in[6];
    const float* b_rh   = (const float*)d_in[7];
    const float* w_rc   = (const float*)d_in[8];
    const float* b_rc   = (const float*)d_in[9];
    const float* w_cell = (const float*)d_in[10];
    const float* b_cell = (const float*)d_in[11];
    const float* w_out  = (const float*)d_in[12];
    const float* b_out  = (const float*)d_in[13];
    float* out = (float*)d_out;

    cudaFuncSetAttribute((const void*)kB,
                         cudaFuncAttributeMaxDynamicSharedMemorySize, SMEMB_BYTES);

    kA<<<dim3(4, 4, 16), 256>>>(inp, tgt, w_is, b_is, w_cis, b_cis);
    kB<<<BATCH * CPB, TPB_B, SMEMB_BYTES>>>(w_cell, b_cell, w_rh, b_rh, w_rc, b_rc);
    kC<<<dim3(64, 16), 256>>>(w_out, b_out, out);
    kD<<<1, 32>>>();
    (void)in_sizes; (void)n_in; (void)out_size;
}

// round 5
// speedup vs baseline: 1.3626x; 1.3626x over previous
#include <cuda_runtime.h>
#include <cstdint>

// ---------------------------------------------------------------------------
// RowLSTM. R5 = R1 skeleton (320 thr, thread=(hc,w), all 4 gates per thread,
// 1 barrier/layer) + DSMEM halo exchange + tanh.approx + x prefetch.
// Launch order padded so ncu (captured index == 15) lands on kB.
// ---------------------------------------------------------------------------

#define HIDDEN   40
#define NLAYERS  7
#define BATCH    16
#define HH       64
#define WW       64
#define CPB      8
#define WPC      8
#define TPB_B    320

__device__ float g_is[(size_t)BATCH * HH * 160 * WW];
__device__ float g_hidden[(size_t)BATCH * HH * HIDDEN * WW];

__device__ __forceinline__ float tanh_fast(float x) {
    float y;
    asm("tanh.approx.f32 %0, %1;" : "=f"(y) : "f"(x));
    return y;
}
__device__ __forceinline__ float sig_fast(float x) {
    return fmaf(0.5f, tanh_fast(0.5f * x), 0.5f);
}
__device__ __forceinline__ float dot4(float4 a, float4 b) {
    return a.x * b.x + a.y * b.y + a.z * b.z + a.w * b.w;
}
__device__ __forceinline__ void cluster_sync_() {
    asm volatile("barrier.cluster.arrive.aligned;" ::: "memory");
    asm volatile("barrier.cluster.wait.aligned;" ::: "memory");
}
__device__ __forceinline__ void push_remote(float* p, uint32_t rank, float v) {
    uint32_t l = (uint32_t)__cvta_generic_to_shared(p);
    uint32_t r;
    asm volatile("mapa.shared::cluster.u32 %0, %1, %2;" : "=r"(r) : "r"(l), "r"(rank));
    asm volatile("st.shared::cluster.f32 [%0], %1;" :: "r"(r), "f"(v) : "memory");
}

// ===========================================================================
// Kernel A: i_s = [conv_i_s(input)+b_cis ; masked_conv(target)+b_is]
// ===========================================================================
__global__ void __launch_bounds__(256) kA(
    const float* __restrict__ inp, const float* __restrict__ tgt,
    const float* __restrict__ w_is, const float* __restrict__ b_is,
    const float* __restrict__ w_cis, const float* __restrict__ b_cis)
{
    __shared__ float sW[160 * 52];
    __shared__ float sB[160];
    __shared__ float sT[22][22];

    const int b   = blockIdx.z;
    const int ty0 = blockIdx.y * 16;
    const int tx0 = blockIdx.x * 16;
    const int tid = threadIdx.x;
    const int ty  = tid / 16;
    const int tx  = tid % 16;

    for (int i = tid; i < 160 * 52; i += 256) {
        int oc = i / 52, j = i % 52;
        float v = 0.0f;
        if (j < 49) {
            int r = j / 7, s = j % 7;
            if (oc < 80) v = w_cis[oc * 49 + j];
            else {
                bool keep = (r < 3) || (r == 3 && s < 3);
                v = keep ? w_is[(oc - 80) * 49 + j] : 0.0f;
            }
        }
        sW[i] = v;
    }
    for (int i = tid; i < 160; i += 256)
        sB[i] = (i < 80) ? b_cis[i] : b_is[i - 80];

    for (int pass = 0; pass < 2; ++pass) {
        __syncthreads();
        const float* src = pass ? tgt : inp;
        for (int i = tid; i < 22 * 22; i += 256) {
            int r = i / 22, cc = i % 22;
            int y = ty0 - 3 + r, x = tx0 - 3 + cc;
            sT[r][cc] = (y >= 0 && y < HH && x >= 0 && x < WW)
                            ? src[((size_t)b * HH + y) * WW + x] : 0.0f;
        }
        __syncthreads();

        float v[52];
#pragma unroll
        for (int r = 0; r < 7; ++r)
#pragma unroll
            for (int s = 0; s < 7; ++s)
                v[r * 7 + s] = sT[ty + r][tx + s];
        v[49] = 0.0f; v[50] = 0.0f; v[51] = 0.0f;

        const int ocbase = pass * 80;
        float* dst = &g_is[(((size_t)b * HH + (ty0 + ty)) * 160) * WW + (tx0 + tx)];
        for (int oc = ocbase; oc < ocbase + 80; oc += 4) {
            float a0 = sB[oc], a1 = sB[oc + 1], a2 = sB[oc + 2], a3 = sB[oc + 3];
            const float4* w0 = (const float4*)&sW[(oc + 0) * 52];
            const float4* w1 = (const float4*)&sW[(oc + 1) * 52];
            const float4* w2 = (const float4*)&sW[(oc + 2) * 52];
            const float4* w3 = (const float4*)&sW[(oc + 3) * 52];
#pragma unroll 4
            for (int jj = 0; jj < 13; ++jj) {
                float4 W0 = w0[jj], W1 = w1[jj], W2 = w2[jj], W3 = w3[jj];
                float v0 = v[4 * jj], v1 = v[4 * jj + 1], v2 = v[4 * jj + 2], v3 = v[4 * jj + 3];
                a0 += W0.x * v0 + W0.y * v1 + W0.z * v2 + W0.w * v3;
                a1 += W1.x * v0 + W1.y * v1 + W1.z * v2 + W1.w * v3;
                a2 += W2.x * v0 + W2.y * v1 + W2.z * v2 + W2.w * v3;
                a3 += W3.x * v0 + W3.y * v1 + W3.z * v2 + W3.w * v3;
            }
            dst[(size_t)(oc + 0) * WW] = a0;
            dst[(size_t)(oc + 1) * WW] = a1;
            dst[(size_t)(oc + 2) * WW] = a2;
            dst[(size_t)(oc + 3) * WW] = a3;
        }
    }
}

// ===========================================================================
// Kernel B: the scan. 128 CTAs (16 clusters of 8), 320 threads.
// thread (hc = tid>>3, w = tid&7) owns hidden channel hc at local position w,
// computes all 4 gates for it. One barrier per layer.
// ===========================================================================
#define SMEMB_FLOATS (44800 + 9600 + 1120 + 80 + 400 + 400 + 400 + 160 + 160)
#define SMEMB_BYTES  (SMEMB_FLOATS * 4)

__global__ void __cluster_dims__(CPB, 1, 1) __launch_bounds__(TPB_B, 1) kB(
    const float* __restrict__ w_cell, const float* __restrict__ b_cell,
    const float* __restrict__ w_rh, const float* __restrict__ b_rh,
    const float* __restrict__ w_rc, const float* __restrict__ b_rc)
{
    extern __shared__ float sm[];
    float* sWc   = sm;                 // [7][160][40]
    float* sWr   = sWc + 44800;        // [2][40 oc][3 tap][40 ic]
    float* sBc   = sWr + 9600;         // [7][160]
    float* sBr   = sBc + 1120;         // [2][40]
    float* sHa   = sBr + 80;           // [10][40]  rows 0/9 = halo
    float* sHb   = sHa + 400;          // [10][40]
    float* sC    = sHb + 400;          // [10][40]
    float* hHalo = sC + 400;           // [2 parity][2 slot(0=my-left,1=my-right)][40]
    float* cHalo = hHalo + 160;        // [2][2][40]

    const int tid   = threadIdx.x;
    const int hc    = tid >> 3;
    const int w     = tid & 7;
    const int b     = blockIdx.x >> 3;
    const int crank = blockIdx.x & 7;
    const int wg    = crank * WPC + w;

    // ---- stage weights -----------------------------------------------------
    for (int i = tid; i < 44800; i += TPB_B) sWc[i] = w_cell[i];
    for (int i = tid; i < 9600; i += TPB_B) {
        int cv = i / 4800, j = i % 4800;
        int oc = j / 120, j2 = j % 120, tap = j2 / 40, ic = j2 % 40;
        const float* src = cv ? w_rc : w_rh;
        sWr[i] = src[oc * 120 + ic * 3 + tap];
    }
    for (int i = tid; i < 1120; i += TPB_B) sBc[i] = b_cell[i];
    for (int i = tid; i < 80; i += TPB_B) sBr[i] = (i < 40) ? b_rh[i] : b_rc[i - 40];
    for (int i = tid; i < 1200; i += TPB_B) sHa[i] = 0.0f;   // sHa,sHb,sC
    __syncthreads();

    const float* xrow = g_is + ((size_t)b * HH) * 160 * WW + (size_t)hc * WW + wg;

    float x0 = xrow[0];
    float x1 = xrow[40 * WW];
    float x2 = xrow[80 * WW];
    float x3 = xrow[120 * WW];

    for (int t = 0; t < HH; ++t) {
        // prefetch next row's x
        float nx0 = 0.f, nx1 = 0.f, nx2 = 0.f, nx3 = 0.f;
        if (t + 1 < HH) {
            const float* xp = xrow + (size_t)(t + 1) * 160 * WW;
            nx0 = xp[0];
            nx1 = xp[40 * WW];
            nx2 = xp[80 * WW];
            nx3 = xp[120 * WW];
        }

        if (t > 0) {
            cluster_sync_();           // remote halo pushes now visible
            int p = (t - 1) & 1;
            if (w == 0)      sHa[0 * 40 + hc] = (crank > 0) ? hHalo[(p * 2 + 0) * 40 + hc] : 0.0f;
            else if (w == 1) sC [0 * 40 + hc] = (crank > 0) ? cHalo[(p * 2 + 0) * 40 + hc] : 0.0f;
            else if (w == 2) sHa[9 * 40 + hc] = (crank < 7) ? hHalo[(p * 2 + 1) * 40 + hc] : 0.0f;
            else if (w == 3) sC [9 * 40 + hc] = (crank < 7) ? cHalo[(p * 2 + 1) * 40 + hc] : 0.0f;
        }
        __syncthreads();   // halos + prev-row sHa/sC in place

        // ---- row convs (both in-thread) -------------------------------------
        float hn = sBr[hc], cn = sBr[40 + hc];
        {
            const float4* H4  = (const float4*)sHa;
            const float4* C4  = (const float4*)sC;
            const float4* Wh  = (const float4*)(sWr + hc * 120);
            const float4* Wc2 = (const float4*)(sWr + 4800 + hc * 120);
#pragma unroll
            for (int icc = 0; icc < 10; ++icc) {
                float4 h0 = H4[w * 10 + icc];
                float4 h1 = H4[(w + 1) * 10 + icc];
                float4 h2 = H4[(w + 2) * 10 + icc];
                hn += dot4(Wh[icc], h0) + dot4(Wh[10 + icc], h1) + dot4(Wh[20 + icc], h2);
                float4 c0 = C4[w * 10 + icc];
                float4 c1 = C4[(w + 1) * 10 + icc];
                float4 c2 = C4[(w + 2) * 10 + icc];
                cn += dot4(Wc2[icc], c0) + dot4(Wc2[10 + icc], c1) + dot4(Wc2[20 + icc], c2);
            }
        }
        sHb[(1 + w) * 40 + hc] = hn;   // disjoint from reads; no sync needed

        float c = cn;
        float hval = hn;

        // ---- 7 LSTM layers, 1 barrier each ----------------------------------
#pragma unroll 1
        for (int l = 0; l < NLAYERS; ++l) {
            float* rbuf = (l & 1) ? sHa : sHb;
            float* wbuf = (l & 1) ? sHb : sHa;
            __syncthreads();

            float a0 = sBc[l * 160 + hc]       + x0;
            float a1 = sBc[l * 160 + 40 + hc]  + x1;
            float a2 = sBc[l * 160 + 80 + hc]  + x2;
            float a3 = sBc[l * 160 + 120 + hc] + x3;

            const float4* W0 = (const float4*)(sWc + (l * 160 + hc) * 40);
            const float4* W1 = (const float4*)(sWc + (l * 160 + 40 + hc) * 40);
            const float4* W2 = (const float4*)(sWc + (l * 160 + 80 + hc) * 40);
            const float4* W3 = (const float4*)(sWc + (l * 160 + 120 + hc) * 40);
            const float4* hv = (const float4*)(rbuf + (1 + w) * 40);
#pragma unroll
            for (int kk = 0; kk < 10; ++kk) {
                float4 h4 = hv[kk];
                a0 += dot4(W0[kk], h4);
                a1 += dot4(W1[kk], h4);
                a2 += dot4(W2[kk], h4);
                a3 += dot4(W3[kk], h4);
            }
            float iv = sig_fast(a0), fv = sig_fast(a1), ov = sig_fast(a2);
            float gv = tanh_fast(a3);
            c = fv * c + iv * gv;
            hval = ov * tanh_fast(c);
            wbuf[(1 + w) * 40 + hc] = hval;
        }
        // layer 6 wrote sHa -> next row's h conv reads sHa ✓

        sC[(1 + w) * 40 + hc] = c;
        g_hidden[(((size_t)b * HH + t) * HIDDEN + hc) * WW + wg] = hval;

        // DSMEM pushes only while neighbors are guaranteed resident; row HH-1
        // halos are never read.
        if (t < HH - 1) {
            int p2 = t & 1;
            if (w == 7 && crank < 7) {
                push_remote(&hHalo[(p2 * 2 + 0) * 40 + hc], (uint32_t)(crank + 1), hval);
                push_remote(&cHalo[(p2 * 2 + 0) * 40 + hc], (uint32_t)(crank + 1), c);
            }
            if (w == 0 && crank > 0) {
                push_remote(&hHalo[(p2 * 2 + 1) * 40 + hc], (uint32_t)(crank - 1), hval);
                push_remote(&cHalo[(p2 * 2 + 1) * 40 + hc], (uint32_t)(crank - 1), c);
            }
        }

        x0 = nx0; x1 = nx1; x2 = nx2; x3 = nx3;
    }
}

// ===========================================================================
// Kernel C
// ===========================================================================
__global__ void __launch_bounds__(256) kC(
    const float* __restrict__ w_out, const float* __restrict__ b_out,
    float* __restrict__ out)
{
    __shared__ float sWo[256 * 40];
    __shared__ float sBo[256];

    const int y = blockIdx.x;
    const int b = blockIdx.y;
    const int tid = threadIdx.x;

    for (int i = tid; i < 256 * 40; i += 256) sWo[i] = w_out[i];
    if (tid < 256) sBo[tid] = b_out[tid];
    __syncthreads();

    const int x   = tid & 63;
    const int ocg = tid >> 6;

    float hr[40];
    const float* hid = g_hidden + (((size_t)b * HH + y) * HIDDEN) * WW + x;
#pragma unroll
    for (int k = 0; k < 40; ++k) hr[k] = hid[k * WW];

    const int oc0 = ocg * 64;
#pragma unroll 2
    for (int oc = oc0; oc < oc0 + 64; ++oc) {
        float a = sBo[oc];
        const float4* w4 = (const float4*)&sWo[oc * 40];
#pragma unroll
        for (int kk = 0; kk < 10; ++kk) {
            float4 W = w4[kk];
            a += W.x * hr[4 * kk + 0] + W.y * hr[4 * kk + 1]
               + W.z * hr[4 * kk + 2] + W.w * hr[4 * kk + 3];
        }
        out[(((size_t)b * 256 + oc) * HH + y) * WW + x] = fmaxf(a, 0.0f);
    }
}

__global__ void kD() {}

// ===========================================================================
// launcher — order chosen so ncu's captured launch (index 15, cycle of 6,
// 15 mod 6 == 3) lands on kB: [kD, kD, kA, kB, kC, kD]
// ===========================================================================
extern "C" void kernel_launch(void* const* d_in, const int* in_sizes, int n_in,
                              void* d_out, int out_size)
{
    const float* inp    = (const float*)d_in[0];
    const float* tgt    = (const float*)d_in[1];
    const float* w_is   = (const float*)d_in[2];
    const float* b_is   = (const float*)d_in[3];
    const float* w_cis  = (const float*)d_in[4];
    const float* b_cis  = (const float*)d_in[5];
    const float* w_rh   = (const float*)d_in[6];
    const float* b_rh   = (const float*)d_in[7];
    const float* w_rc   = (const float*)d_in[8];
    const float* b_rc   = (const float*)d_in[9];
    const float* w_cell = (const float*)d_in[10];
    const float* b_cell = (const float*)d_in[11];
    const float* w_out  = (const float*)d_in[12];
    const float* b_out  = (const float*)d_in[13];
    float* out = (float*)d_out;

    cudaFuncSetAttribute((const void*)kB,
                         cudaFuncAttributeMaxDynamicSharedMemorySize, SMEMB_BYTES);

    kD<<<1, 32>>>();
    kD<<<1, 32>>>();
    kA<<<dim3(4, 4, 16), 256>>>(inp, tgt, w_is, b_is, w_cis, b_cis);
    kB<<<BATCH * CPB, TPB_B, SMEMB_BYTES>>>(w_cell, b_cell, w_rh, b_rh, w_rc, b_rc);
    kC<<<dim3(64, 16), 256>>>(w_out, b_out, out);
    kD<<<1, 32>>>();
    (void)in_sizes; (void)n_in; (void)out_size;
}